// round 3
// baseline (speedup 1.0000x reference)
#include <cuda_runtime.h>
#include <cuda_bf16.h>
#include <cstddef>

// Problem constants
#define BB   2
#define NN   2048
#define CC   1024
#define HH   16
#define DD   64
#define SCALE 0.125f   // 64^-0.5

// Scratch: Q,K,V,O each [B][H][N][D] = 4,194,304 floats (16 MB)
__device__ float g_q[BB * HH * NN * DD];
__device__ float g_k[BB * HH * NN * DD];
__device__ float g_v[BB * HH * NN * DD];
__device__ float g_o[BB * HH * NN * DD];

// ---------------------------------------------------------------------------
// Kernel 1: QKV GEMM.  out[m][j] = sum_k x[m][k] * w_qkv[j][k]
// m in [0,4096), j in [0,3072).  Epilogue scatters j -> (which, h, d) into
// g_q / g_k / g_v laid out [B][H][N][D].
// Tiling: BM=128, BN=128, BK=16, 256 threads, 8x8 per-thread micro-tile
// (col groups {4*tx..4*tx+3} and {64+4*tx..}).
// ---------------------------------------------------------------------------
__global__ __launch_bounds__(256) void qkv_gemm_kernel(
    const float* __restrict__ x, const float* __restrict__ w)
{
    __shared__ __align__(16) float As[16 * 132];
    __shared__ __align__(16) float Bs[16 * 132];

    const int tid = threadIdx.x;
    const int tx = tid & 15;
    const int ty = tid >> 4;
    const int m0 = blockIdx.y * 128;
    const int n0 = blockIdx.x * 128;

    float acc[8][8];
#pragma unroll
    for (int i = 0; i < 8; ++i)
#pragma unroll
        for (int j = 0; j < 8; ++j) acc[i][j] = 0.0f;

    for (int k0 = 0; k0 < CC; k0 += 16) {
#pragma unroll
        for (int it = 0; it < 2; ++it) {
            const int flat = it * 256 + tid;        // 0..511
            const int row  = flat >> 2;             // 0..127
            const int kv   = (flat & 3) * 4;        // 0,4,8,12
            float4 av = *(const float4*)&x[(size_t)(m0 + row) * CC + k0 + kv];
            As[(kv + 0) * 132 + row] = av.x;
            As[(kv + 1) * 132 + row] = av.y;
            As[(kv + 2) * 132 + row] = av.z;
            As[(kv + 3) * 132 + row] = av.w;
            float4 bv = *(const float4*)&w[(size_t)(n0 + row) * CC + k0 + kv];
            Bs[(kv + 0) * 132 + row] = bv.x;
            Bs[(kv + 1) * 132 + row] = bv.y;
            Bs[(kv + 2) * 132 + row] = bv.z;
            Bs[(kv + 3) * 132 + row] = bv.w;
        }
        __syncthreads();

#pragma unroll
        for (int kk = 0; kk < 16; ++kk) {
            float4 a0 = *(const float4*)&As[kk * 132 + ty * 8];
            float4 a1 = *(const float4*)&As[kk * 132 + ty * 8 + 4];
            float4 b0 = *(const float4*)&Bs[kk * 132 + tx * 4];
            float4 b1 = *(const float4*)&Bs[kk * 132 + 64 + tx * 4];
            float a[8] = {a0.x, a0.y, a0.z, a0.w, a1.x, a1.y, a1.z, a1.w};
            float b[8] = {b0.x, b0.y, b0.z, b0.w, b1.x, b1.y, b1.z, b1.w};
#pragma unroll
            for (int i = 0; i < 8; ++i)
#pragma unroll
                for (int j = 0; j < 8; ++j) acc[i][j] += a[i] * b[j];
        }
        __syncthreads();
    }

    // Epilogue: scatter into Q/K/V [B][H][N][D]
#pragma unroll
    for (int i = 0; i < 8; ++i) {
        const int m  = m0 + ty * 8 + i;
        const int bb = m >> 11;
        const int nn = m & 2047;
#pragma unroll
        for (int j = 0; j < 8; ++j) {
            const int col = (j < 4) ? (tx * 4 + j) : (64 + tx * 4 + (j - 4));
            const int jg  = n0 + col;
            const int which = jg >> 10;
            const int hh = (jg >> 6) & 15;
            const int dd = jg & 63;
            float* dst = (which == 0) ? g_q : (which == 1) ? g_k : g_v;
            dst[((size_t)(bb * HH + hh) * NN + nn) * DD + dd] = acc[i][j];
        }
    }
}

// ---------------------------------------------------------------------------
// Kernel 2: flash attention per (b,h).  Q tile = 64 rows, key tiles of 64.
// Online softmax with running max/sum in shared memory.
// ---------------------------------------------------------------------------
__global__ __launch_bounds__(256) void attn_kernel()
{
    extern __shared__ __align__(16) float sm[];
    float* Qs  = sm;                 // 64 x 65
    float* Ks  = sm + 4160;          // 64 x 65
    float* Vs  = sm + 8320;          // 64 x 65
    float* Ss  = sm + 12480;         // 64 x 65
    float* m_s = sm + 16640;         // 64
    float* l_s = sm + 16704;         // 64
    float* c_s = sm + 16768;         // 64

    const int tid = threadIdx.x;
    const int bh  = blockIdx.y;
    const int q0  = blockIdx.x * 64;
    const size_t base = (size_t)bh * NN * DD;

    // Load + scale Q tile
#pragma unroll
    for (int it = 0; it < 4; ++it) {
        const int flat = it * 256 + tid;     // 0..1023
        const int row  = flat >> 4;          // 0..63
        const int dv   = (flat & 15) * 4;    // 0..60
        float4 v = *(const float4*)&g_q[base + (size_t)(q0 + row) * DD + dv];
        Qs[row * 65 + dv + 0] = v.x * SCALE;
        Qs[row * 65 + dv + 1] = v.y * SCALE;
        Qs[row * 65 + dv + 2] = v.z * SCALE;
        Qs[row * 65 + dv + 3] = v.w * SCALE;
    }
    if (tid < 64) { m_s[tid] = -1e30f; l_s[tid] = 0.0f; }

    float o[4][4];
#pragma unroll
    for (int i = 0; i < 4; ++i)
#pragma unroll
        for (int j = 0; j < 4; ++j) o[i][j] = 0.0f;

    const int tr4 = (tid >> 4) * 4;   // rows (layout A)
    const int tc4 = (tid & 15) * 4;   // cols (layout A)
    const int rB  = tid >> 2;         // row (layout B)
    const int g16 = (tid & 3) * 16;   // col group (layout B)

    for (int kt = 0; kt < NN / 64; ++kt) {
        __syncthreads();   // protects Ks/Vs/Ss from previous iteration
        const int k0 = kt * 64;
#pragma unroll
        for (int it = 0; it < 4; ++it) {
            const int flat = it * 256 + tid;
            const int row  = flat >> 4;
            const int dv   = (flat & 15) * 4;
            float4 kv4 = *(const float4*)&g_k[base + (size_t)(k0 + row) * DD + dv];
            Ks[row * 65 + dv + 0] = kv4.x;
            Ks[row * 65 + dv + 1] = kv4.y;
            Ks[row * 65 + dv + 2] = kv4.z;
            Ks[row * 65 + dv + 3] = kv4.w;
            float4 vv4 = *(const float4*)&g_v[base + (size_t)(k0 + row) * DD + dv];
            Vs[row * 65 + dv + 0] = vv4.x;
            Vs[row * 65 + dv + 1] = vv4.y;
            Vs[row * 65 + dv + 2] = vv4.z;
            Vs[row * 65 + dv + 3] = vv4.w;
        }
        __syncthreads();

        // S = Qs @ Ks^T  (4x4 micro-tile per thread)
        float s[4][4];
#pragma unroll
        for (int i = 0; i < 4; ++i)
#pragma unroll
            for (int j = 0; j < 4; ++j) s[i][j] = 0.0f;

#pragma unroll 4
        for (int d = 0; d < 64; ++d) {
            float qa[4], kb[4];
#pragma unroll
            for (int i = 0; i < 4; ++i) qa[i] = Qs[(tr4 + i) * 65 + d];
#pragma unroll
            for (int j = 0; j < 4; ++j) kb[j] = Ks[(tc4 + j) * 65 + d];
#pragma unroll
            for (int i = 0; i < 4; ++i)
#pragma unroll
                for (int j = 0; j < 4; ++j) s[i][j] += qa[i] * kb[j];
        }
#pragma unroll
        for (int i = 0; i < 4; ++i)
#pragma unroll
            for (int j = 0; j < 4; ++j)
                Ss[(tr4 + i) * 65 + tc4 + j] = s[i][j];
        __syncthreads();

        // Online softmax (layout B: 4 lanes per row, 16 cols each)
        {
            const int rb = rB * 65;
            float p[16];
            float mx = -1e30f;
#pragma unroll
            for (int c = 0; c < 16; ++c) {
                p[c] = Ss[rb + g16 + c];
                mx = fmaxf(mx, p[c]);
            }
            mx = fmaxf(mx, __shfl_xor_sync(0xffffffffu, mx, 1));
            mx = fmaxf(mx, __shfl_xor_sync(0xffffffffu, mx, 2));
            const float m_old = m_s[rB];
            const float m_new = fmaxf(m_old, mx);
            float ls = 0.0f;
#pragma unroll
            for (int c = 0; c < 16; ++c) {
                p[c] = __expf(p[c] - m_new);
                ls += p[c];
                Ss[rb + g16 + c] = p[c];
            }
            ls += __shfl_xor_sync(0xffffffffu, ls, 1);
            ls += __shfl_xor_sync(0xffffffffu, ls, 2);
            if ((tid & 3) == 0) {
                const float corr = (m_old <= -1e29f) ? 0.0f : __expf(m_old - m_new);
                l_s[rB] = l_s[rB] * corr + ls;
                m_s[rB] = m_new;
                c_s[rB] = corr;
            }
        }
        __syncthreads();

        // Rescale accumulators, then O += P @ V (layout A)
#pragma unroll
        for (int i = 0; i < 4; ++i) {
            const float cf = c_s[tr4 + i];
#pragma unroll
            for (int j = 0; j < 4; ++j) o[i][j] *= cf;
        }
#pragma unroll 4
        for (int k = 0; k < 64; ++k) {
            float pa[4], vb[4];
#pragma unroll
            for (int i = 0; i < 4; ++i) pa[i] = Ss[(tr4 + i) * 65 + k];
#pragma unroll
            for (int j = 0; j < 4; ++j) vb[j] = Vs[k * 65 + tc4 + j];
#pragma unroll
            for (int i = 0; i < 4; ++i)
#pragma unroll
                for (int j = 0; j < 4; ++j) o[i][j] += pa[i] * vb[j];
        }
    }

    // Final normalize + store (l_s visible: written before last in-loop barrier)
#pragma unroll
    for (int i = 0; i < 4; ++i) {
        const float inv = 1.0f / l_s[tr4 + i];
#pragma unroll
        for (int j = 0; j < 4; ++j)
            g_o[base + (size_t)(q0 + tr4 + i) * DD + tc4 + j] = o[i][j] * inv;
    }
}

// ---------------------------------------------------------------------------
// Kernel 3: output projection.  out[m][j] = sum_k O[m][k]*w_proj[j][k] + b[j]
// A gathered from g_o [B][H][N][D] (k = h*64+d).
// ---------------------------------------------------------------------------
__global__ __launch_bounds__(256) void proj_gemm_kernel(
    const float* __restrict__ w, const float* __restrict__ bias,
    float* __restrict__ out)
{
    __shared__ __align__(16) float As[16 * 132];
    __shared__ __align__(16) float Bs[16 * 132];

    const int tid = threadIdx.x;
    const int tx = tid & 15;
    const int ty = tid >> 4;
    const int m0 = blockIdx.y * 128;
    const int n0 = blockIdx.x * 128;

    float acc[8][8];
#pragma unroll
    for (int i = 0; i < 8; ++i)
#pragma unroll
        for (int j = 0; j < 8; ++j) acc[i][j] = 0.0f;

    for (int k0 = 0; k0 < CC; k0 += 16) {
#pragma unroll
        for (int it = 0; it < 2; ++it) {
            const int flat = it * 256 + tid;
            const int row  = flat >> 2;
            const int kv   = (flat & 3) * 4;
            const int m    = m0 + row;
            const int bb   = m >> 11;
            const int nn   = m & 2047;
            const int k    = k0 + kv;
            const int hh   = k >> 6;
            const int dd   = k & 63;
            float4 av = *(const float4*)&g_o[((size_t)(bb * HH + hh) * NN + nn) * DD + dd];
            As[(kv + 0) * 132 + row] = av.x;
            As[(kv + 1) * 132 + row] = av.y;
            As[(kv + 2) * 132 + row] = av.z;
            As[(kv + 3) * 132 + row] = av.w;
            float4 bv = *(const float4*)&w[(size_t)(n0 + row) * CC + k0 + kv];
            Bs[(kv + 0) * 132 + row] = bv.x;
            Bs[(kv + 1) * 132 + row] = bv.y;
            Bs[(kv + 2) * 132 + row] = bv.z;
            Bs[(kv + 3) * 132 + row] = bv.w;
        }
        __syncthreads();

#pragma unroll
        for (int kk = 0; kk < 16; ++kk) {
            float4 a0 = *(const float4*)&As[kk * 132 + ty * 8];
            float4 a1 = *(const float4*)&As[kk * 132 + ty * 8 + 4];
            float4 b0 = *(const float4*)&Bs[kk * 132 + tx * 4];
            float4 b1 = *(const float4*)&Bs[kk * 132 + 64 + tx * 4];
            float a[8] = {a0.x, a0.y, a0.z, a0.w, a1.x, a1.y, a1.z, a1.w};
            float b[8] = {b0.x, b0.y, b0.z, b0.w, b1.x, b1.y, b1.z, b1.w};
#pragma unroll
            for (int i = 0; i < 8; ++i)
#pragma unroll
                for (int j = 0; j < 8; ++j) acc[i][j] += a[i] * b[j];
        }
        __syncthreads();
    }

#pragma unroll
    for (int i = 0; i < 8; ++i) {
        const int m = m0 + ty * 8 + i;
#pragma unroll
        for (int j = 0; j < 8; ++j) {
            const int col = (j < 4) ? (tx * 4 + j) : (64 + tx * 4 + (j - 4));
            const int jg  = n0 + col;
            out[(size_t)m * CC + jg] = acc[i][j] + bias[jg];
        }
    }
}

// ---------------------------------------------------------------------------
extern "C" void kernel_launch(void* const* d_in, const int* in_sizes, int n_in,
                              void* d_out, int out_size)
{
    (void)in_sizes; (void)n_in; (void)out_size;
    const float* x      = (const float*)d_in[0];   // [2,2048,1024]
    const float* w_qkv  = (const float*)d_in[1];   // [3072,1024]
    const float* w_proj = (const float*)d_in[2];   // [1024,1024]
    const float* b_proj = (const float*)d_in[3];   // [1024]
    float* out = (float*)d_out;                    // [2,2048,1024]

    // QKV projection + scatter to [B,H,N,D]
    qkv_gemm_kernel<<<dim3(3 * CC / 128, BB * NN / 128), 256>>>(x, w_qkv);

    // Flash attention per (b,h)
    const size_t attn_smem = 16832 * sizeof(float);  // 67,328 B
    cudaFuncSetAttribute(attn_kernel,
                         cudaFuncAttributeMaxDynamicSharedMemorySize,
                         (int)attn_smem);
    attn_kernel<<<dim3(NN / 64, BB * HH), 256, attn_smem>>>();

    // Output projection + bias
    proj_gemm_kernel<<<dim3(CC / 128, BB * NN / 128), 256>>>(w_proj, b_proj, out);
}

// round 12
// speedup vs baseline: 1.6633x; 1.6633x over previous
#include <cuda_runtime.h>
#include <cuda_bf16.h>
#include <cstddef>

// Problem constants
#define BB   2
#define NN   2048
#define CC   1024
#define HH   16
#define DD   64
#define SCALE 0.125f   // 64^-0.5

// Scratch: Q,K,V,O each [B][H][N][D] = 4,194,304 floats (16 MB)
__device__ float g_q[BB * HH * NN * DD];
__device__ float g_k[BB * HH * NN * DD];
__device__ float g_v[BB * HH * NN * DD];
__device__ float g_o[BB * HH * NN * DD];

__device__ __forceinline__ unsigned f2tf32(float f) {
    unsigned u;
    asm("cvt.rna.tf32.f32 %0, %1;" : "=r"(u) : "f"(f));
    return u;
}

// 3xTF32 split: x ~= hi + lo, both tf32-representable.
__device__ __forceinline__ void split_tf32(float x, unsigned& hi, unsigned& lo) {
    hi = f2tf32(x);
    lo = f2tf32(x - __uint_as_float(hi));
}

__device__ __forceinline__ void mma_tf32(float& d0, float& d1, float& d2, float& d3,
                                         unsigned a0, unsigned a1, unsigned a2, unsigned a3,
                                         unsigned b0, unsigned b1) {
    asm volatile(
        "mma.sync.aligned.m16n8k8.row.col.f32.tf32.tf32.f32 "
        "{%0,%1,%2,%3}, {%4,%5,%6,%7}, {%8,%9}, {%0,%1,%2,%3};\n"
        : "+f"(d0), "+f"(d1), "+f"(d2), "+f"(d3)
        : "r"(a0), "r"(a1), "r"(a2), "r"(a3), "r"(b0), "r"(b1));
}

// ---------------------------------------------------------------------------
// GEMM tiles (3xTF32 mma): BM=128, BN=128, BK=16; 8 warps in 2x4 grid,
// warp tile 64x32 (4 m16-tiles x 4 n8-tiles).
// Smem: A as [k][m] pitch 132, B as [k][n] pitch 132, hi+lo each.
// ---------------------------------------------------------------------------
#define GP 132

// Shared mainloop body (acc layout: [mt][nt][reg])
#define GEMM_MAINLOOP(Ah, Al, Bh, Bl, acc, warp_m, warp_n, g, t)                 \
    for (int ks = 0; ks < 2; ++ks) {                                             \
        unsigned ah[4][4], al[4][4], bh[4][2], bl[4][2];                         \
        _Pragma("unroll")                                                        \
        for (int mt = 0; mt < 4; ++mt) {                                         \
            const int mr = warp_m * 64 + mt * 16;                                \
            ah[mt][0] = Ah[(ks * 8 + t)     * GP + mr + g];                      \
            ah[mt][1] = Ah[(ks * 8 + t)     * GP + mr + g + 8];                  \
            ah[mt][2] = Ah[(ks * 8 + t + 4) * GP + mr + g];                      \
            ah[mt][3] = Ah[(ks * 8 + t + 4) * GP + mr + g + 8];                  \
            al[mt][0] = Al[(ks * 8 + t)     * GP + mr + g];                      \
            al[mt][1] = Al[(ks * 8 + t)     * GP + mr + g + 8];                  \
            al[mt][2] = Al[(ks * 8 + t + 4) * GP + mr + g];                      \
            al[mt][3] = Al[(ks * 8 + t + 4) * GP + mr + g + 8];                  \
        }                                                                        \
        _Pragma("unroll")                                                        \
        for (int nt = 0; nt < 4; ++nt) {                                         \
            const int nc = warp_n * 32 + nt * 8;                                 \
            bh[nt][0] = Bh[(ks * 8 + t)     * GP + nc + g];                      \
            bh[nt][1] = Bh[(ks * 8 + t + 4) * GP + nc + g];                      \
            bl[nt][0] = Bl[(ks * 8 + t)     * GP + nc + g];                      \
            bl[nt][1] = Bl[(ks * 8 + t + 4) * GP + nc + g];                      \
        }                                                                        \
        _Pragma("unroll")                                                        \
        for (int mt = 0; mt < 4; ++mt)                                           \
            _Pragma("unroll")                                                    \
            for (int nt = 0; nt < 4; ++nt) {                                     \
                mma_tf32(acc[mt][nt][0], acc[mt][nt][1], acc[mt][nt][2],         \
                         acc[mt][nt][3], al[mt][0], al[mt][1], al[mt][2],        \
                         al[mt][3], bh[nt][0], bh[nt][1]);                       \
                mma_tf32(acc[mt][nt][0], acc[mt][nt][1], acc[mt][nt][2],         \
                         acc[mt][nt][3], ah[mt][0], ah[mt][1], ah[mt][2],        \
                         ah[mt][3], bl[nt][0], bl[nt][1]);                       \
                mma_tf32(acc[mt][nt][0], acc[mt][nt][1], acc[mt][nt][2],         \
                         acc[mt][nt][3], ah[mt][0], ah[mt][1], ah[mt][2],        \
                         ah[mt][3], bh[nt][0], bh[nt][1]);                       \
            }                                                                    \
    }

// ---------------------------------------------------------------------------
// Kernel 1: QKV GEMM (3xTF32 mma).  out[m][j] = sum_k x[m][k]*w_qkv[j][k]
// Epilogue scatters j -> (which, h, d) into g_q/g_k/g_v [B][H][N][D].
// ---------------------------------------------------------------------------
__global__ __launch_bounds__(256) void qkv_gemm_kernel(
    const float* __restrict__ x, const float* __restrict__ w)
{
    __shared__ __align__(16) unsigned Ah[16 * GP], Al[16 * GP];
    __shared__ __align__(16) unsigned Bh[16 * GP], Bl[16 * GP];

    const int tid  = threadIdx.x;
    const int wid  = tid >> 5;
    const int lane = tid & 31;
    const int g    = lane >> 2;
    const int t    = lane & 3;
    const int warp_m = wid >> 2;  // 0..1
    const int warp_n = wid & 3;   // 0..3
    const int m0 = blockIdx.y * 128;
    const int n0 = blockIdx.x * 128;

    float acc[4][4][4];
#pragma unroll
    for (int mt = 0; mt < 4; ++mt)
#pragma unroll
        for (int nt = 0; nt < 4; ++nt)
#pragma unroll
            for (int r = 0; r < 4; ++r) acc[mt][nt][r] = 0.0f;

    for (int k0 = 0; k0 < CC; k0 += 16) {
#pragma unroll
        for (int it = 0; it < 2; ++it) {
            const int flat = it * 256 + tid;        // 0..511
            const int row  = flat >> 2;             // 0..127
            const int kv   = (flat & 3) * 4;        // 0,4,8,12
            float4 av = *(const float4*)&x[(size_t)(m0 + row) * CC + k0 + kv];
            split_tf32(av.x, Ah[(kv + 0) * GP + row], Al[(kv + 0) * GP + row]);
            split_tf32(av.y, Ah[(kv + 1) * GP + row], Al[(kv + 1) * GP + row]);
            split_tf32(av.z, Ah[(kv + 2) * GP + row], Al[(kv + 2) * GP + row]);
            split_tf32(av.w, Ah[(kv + 3) * GP + row], Al[(kv + 3) * GP + row]);
            float4 bv = *(const float4*)&w[(size_t)(n0 + row) * CC + k0 + kv];
            split_tf32(bv.x, Bh[(kv + 0) * GP + row], Bl[(kv + 0) * GP + row]);
            split_tf32(bv.y, Bh[(kv + 1) * GP + row], Bl[(kv + 1) * GP + row]);
            split_tf32(bv.z, Bh[(kv + 2) * GP + row], Bl[(kv + 2) * GP + row]);
            split_tf32(bv.w, Bh[(kv + 3) * GP + row], Bl[(kv + 3) * GP + row]);
        }
        __syncthreads();
        GEMM_MAINLOOP(Ah, Al, Bh, Bl, acc, warp_m, warp_n, g, t)
        __syncthreads();
    }

    // Epilogue: scatter C-frags into Q/K/V [B][H][N][D]
#pragma unroll
    for (int mt = 0; mt < 4; ++mt) {
#pragma unroll
        for (int nt = 0; nt < 4; ++nt) {
#pragma unroll
            for (int r = 0; r < 4; ++r) {
                const int m  = m0 + warp_m * 64 + mt * 16 + g + ((r >= 2) ? 8 : 0);
                const int jg = n0 + warp_n * 32 + nt * 8 + 2 * t + (r & 1);
                const int bb = m >> 11;
                const int nn = m & 2047;
                const int which = jg >> 10;
                const int hh = (jg >> 6) & 15;
                const int dd = jg & 63;
                float* dst = (which == 0) ? g_q : (which == 1) ? g_k : g_v;
                dst[((size_t)(bb * HH + hh) * NN + nn) * DD + dd] = acc[mt][nt][r];
            }
        }
    }
}

// ---------------------------------------------------------------------------
// Kernel 2: flash attention with tf32 mma.sync (m16n8k8).  [unchanged]
// Q tile = 128 rows (8 warps x 16), key tile = 64. Online softmax in regs.
// smem (u32 tf32 bits): Ks[64][68], Vs[64][68], Ps[128][68]  = 69632 B
// ---------------------------------------------------------------------------
#define PITCH 68
#define KS_OFF 0
#define VS_OFF (64 * PITCH)
#define PS_OFF (128 * PITCH)
#define ATTN_SMEM_BYTES ((PS_OFF + 128 * PITCH) * 4)

__global__ __launch_bounds__(256) void attn_mma_kernel()
{
    extern __shared__ __align__(16) unsigned sm_u[];
    unsigned* Ks = sm_u + KS_OFF;
    unsigned* Vs = sm_u + VS_OFF;
    unsigned* Ps = sm_u + PS_OFF;

    const int tid  = threadIdx.x;
    const int wid  = tid >> 5;
    const int lane = tid & 31;
    const int g    = lane >> 2;   // groupID (row within m16 tile)
    const int t    = lane & 3;    // thread in group
    const int bh   = blockIdx.y;
    const int q0   = blockIdx.x * 128;
    const int mrow = wid * 16;    // warp's row base within Q tile
    const size_t base = (size_t)bh * NN * DD;

    // --- Load Q fragments once (16x64 per warp), fold SCALE, cvt tf32 ---
    unsigned qf[8][4];
    {
        const float* Qg = g_q + base + (size_t)(q0 + mrow) * DD;
#pragma unroll
        for (int kk = 0; kk < 8; ++kk) {
            qf[kk][0] = f2tf32(Qg[(size_t)(g)     * DD + kk * 8 + t]     * SCALE);
            qf[kk][1] = f2tf32(Qg[(size_t)(g + 8) * DD + kk * 8 + t]     * SCALE);
            qf[kk][2] = f2tf32(Qg[(size_t)(g)     * DD + kk * 8 + t + 4] * SCALE);
            qf[kk][3] = f2tf32(Qg[(size_t)(g + 8) * DD + kk * 8 + t + 4] * SCALE);
        }
    }

    float o[8][4];
#pragma unroll
    for (int nt = 0; nt < 8; ++nt)
#pragma unroll
        for (int r = 0; r < 4; ++r) o[nt][r] = 0.0f;
    float m0v = -1e30f, m1v = -1e30f, l0 = 0.0f, l1 = 0.0f;

    for (int kt = 0; kt < NN / 64; ++kt) {
        const int k0 = kt * 64;
        __syncthreads();   // protect Ks/Vs reuse
        // --- Stage K,V tile (64x64) into smem as tf32 bits ---
#pragma unroll
        for (int it = 0; it < 4; ++it) {
            const int flat = it * 256 + tid;      // 0..1023
            const int row  = flat >> 4;           // 0..63
            const int c4   = (flat & 15) * 4;     // 0..60
            float4 kv4 = *(const float4*)&g_k[base + (size_t)(k0 + row) * DD + c4];
            uint4 ku;
            ku.x = f2tf32(kv4.x); ku.y = f2tf32(kv4.y);
            ku.z = f2tf32(kv4.z); ku.w = f2tf32(kv4.w);
            *(uint4*)&Ks[row * PITCH + c4] = ku;
            float4 vv4 = *(const float4*)&g_v[base + (size_t)(k0 + row) * DD + c4];
            uint4 vu;
            vu.x = f2tf32(vv4.x); vu.y = f2tf32(vv4.y);
            vu.z = f2tf32(vv4.z); vu.w = f2tf32(vv4.w);
            *(uint4*)&Vs[row * PITCH + c4] = vu;
        }
        __syncthreads();

        // --- S = Q @ K^T : 8 n-tiles x 8 k-steps of m16n8k8 ---
        float s[8][4];
#pragma unroll
        for (int nt = 0; nt < 8; ++nt)
#pragma unroll
            for (int r = 0; r < 4; ++r) s[nt][r] = 0.0f;

#pragma unroll
        for (int kk = 0; kk < 8; ++kk) {
#pragma unroll
            for (int nt = 0; nt < 8; ++nt) {
                const unsigned b0 = Ks[(nt * 8 + g) * PITCH + kk * 8 + t];
                const unsigned b1 = Ks[(nt * 8 + g) * PITCH + kk * 8 + t + 4];
                mma_tf32(s[nt][0], s[nt][1], s[nt][2], s[nt][3],
                         qf[kk][0], qf[kk][1], qf[kk][2], qf[kk][3], b0, b1);
            }
        }

        // --- Online softmax in registers ---
        float mx0 = -1e30f, mx1 = -1e30f;
#pragma unroll
        for (int nt = 0; nt < 8; ++nt) {
            mx0 = fmaxf(mx0, fmaxf(s[nt][0], s[nt][1]));
            mx1 = fmaxf(mx1, fmaxf(s[nt][2], s[nt][3]));
        }
        mx0 = fmaxf(mx0, __shfl_xor_sync(0xffffffffu, mx0, 1));
        mx0 = fmaxf(mx0, __shfl_xor_sync(0xffffffffu, mx0, 2));
        mx1 = fmaxf(mx1, __shfl_xor_sync(0xffffffffu, mx1, 1));
        mx1 = fmaxf(mx1, __shfl_xor_sync(0xffffffffu, mx1, 2));

        const float m0n = fmaxf(m0v, mx0);
        const float m1n = fmaxf(m1v, mx1);
        const float corr0 = __expf(m0v - m0n);
        const float corr1 = __expf(m1v - m1n);
        m0v = m0n; m1v = m1n;

        float sum0 = 0.0f, sum1 = 0.0f;
#pragma unroll
        for (int nt = 0; nt < 8; ++nt) {
            s[nt][0] = __expf(s[nt][0] - m0n);
            s[nt][1] = __expf(s[nt][1] - m0n);
            s[nt][2] = __expf(s[nt][2] - m1n);
            s[nt][3] = __expf(s[nt][3] - m1n);
            sum0 += s[nt][0] + s[nt][1];
            sum1 += s[nt][2] + s[nt][3];
        }
        sum0 += __shfl_xor_sync(0xffffffffu, sum0, 1);
        sum0 += __shfl_xor_sync(0xffffffffu, sum0, 2);
        sum1 += __shfl_xor_sync(0xffffffffu, sum1, 1);
        sum1 += __shfl_xor_sync(0xffffffffu, sum1, 2);
        l0 = l0 * corr0 + sum0;
        l1 = l1 * corr1 + sum1;

        // Rescale O accumulators (row layout matches: c0,c1 -> row g; c2,c3 -> g+8)
#pragma unroll
        for (int nt = 0; nt < 8; ++nt) {
            o[nt][0] *= corr0; o[nt][1] *= corr0;
            o[nt][2] *= corr1; o[nt][3] *= corr1;
        }

        // --- Write P (tf32 bits) to this warp's smem stripe, warp-local ---
#pragma unroll
        for (int nt = 0; nt < 8; ++nt) {
            Ps[(mrow + g)     * PITCH + nt * 8 + 2 * t]     = f2tf32(s[nt][0]);
            Ps[(mrow + g)     * PITCH + nt * 8 + 2 * t + 1] = f2tf32(s[nt][1]);
            Ps[(mrow + g + 8) * PITCH + nt * 8 + 2 * t]     = f2tf32(s[nt][2]);
            Ps[(mrow + g + 8) * PITCH + nt * 8 + 2 * t + 1] = f2tf32(s[nt][3]);
        }
        __syncwarp();

        // --- O += P @ V ---
#pragma unroll
        for (int kk = 0; kk < 8; ++kk) {
            const unsigned a0 = Ps[(mrow + g)     * PITCH + kk * 8 + t];
            const unsigned a1 = Ps[(mrow + g + 8) * PITCH + kk * 8 + t];
            const unsigned a2 = Ps[(mrow + g)     * PITCH + kk * 8 + t + 4];
            const unsigned a3 = Ps[(mrow + g + 8) * PITCH + kk * 8 + t + 4];
#pragma unroll
            for (int dn = 0; dn < 8; ++dn) {
                const unsigned b0 = Vs[(kk * 8 + t)     * PITCH + dn * 8 + g];
                const unsigned b1 = Vs[(kk * 8 + t + 4) * PITCH + dn * 8 + g];
                mma_tf32(o[dn][0], o[dn][1], o[dn][2], o[dn][3],
                         a0, a1, a2, a3, b0, b1);
            }
        }
        __syncwarp();   // keep Ps stable until all lanes consumed it
    }

    // --- Epilogue: normalize and store O tile ---
    const float inv0 = 1.0f / l0;
    const float inv1 = 1.0f / l1;
    float* Og = g_o + base + (size_t)(q0 + mrow) * DD;
#pragma unroll
    for (int nt = 0; nt < 8; ++nt) {
        Og[(size_t)(g)     * DD + nt * 8 + 2 * t]     = o[nt][0] * inv0;
        Og[(size_t)(g)     * DD + nt * 8 + 2 * t + 1] = o[nt][1] * inv0;
        Og[(size_t)(g + 8) * DD + nt * 8 + 2 * t]     = o[nt][2] * inv1;
        Og[(size_t)(g + 8) * DD + nt * 8 + 2 * t + 1] = o[nt][3] * inv1;
    }
}

// ---------------------------------------------------------------------------
// Kernel 3: output projection (3xTF32 mma).  out = O @ w_proj^T + b
// A gathered from g_o [B][H][N][D] (k = h*64+d).
// ---------------------------------------------------------------------------
__global__ __launch_bounds__(256) void proj_gemm_kernel(
    const float* __restrict__ w, const float* __restrict__ bias,
    float* __restrict__ out)
{
    __shared__ __align__(16) unsigned Ah[16 * GP], Al[16 * GP];
    __shared__ __align__(16) unsigned Bh[16 * GP], Bl[16 * GP];

    const int tid  = threadIdx.x;
    const int wid  = tid >> 5;
    const int lane = tid & 31;
    const int g    = lane >> 2;
    const int t    = lane & 3;
    const int warp_m = wid >> 2;
    const int warp_n = wid & 3;
    const int m0 = blockIdx.y * 128;
    const int n0 = blockIdx.x * 128;

    float acc[4][4][4];
#pragma unroll
    for (int mt = 0; mt < 4; ++mt)
#pragma unroll
        for (int nt = 0; nt < 4; ++nt)
#pragma unroll
            for (int r = 0; r < 4; ++r) acc[mt][nt][r] = 0.0f;

    for (int k0 = 0; k0 < CC; k0 += 16) {
#pragma unroll
        for (int it = 0; it < 2; ++it) {
            const int flat = it * 256 + tid;
            const int row  = flat >> 2;
            const int kv   = (flat & 3) * 4;
            const int m    = m0 + row;
            const int bb   = m >> 11;
            const int nn   = m & 2047;
            const int k    = k0 + kv;
            const int hh   = k >> 6;
            const int dd   = k & 63;
            float4 av = *(const float4*)&g_o[((size_t)(bb * HH + hh) * NN + nn) * DD + dd];
            split_tf32(av.x, Ah[(kv + 0) * GP + row], Al[(kv + 0) * GP + row]);
            split_tf32(av.y, Ah[(kv + 1) * GP + row], Al[(kv + 1) * GP + row]);
            split_tf32(av.z, Ah[(kv + 2) * GP + row], Al[(kv + 2) * GP + row]);
            split_tf32(av.w, Ah[(kv + 3) * GP + row], Al[(kv + 3) * GP + row]);
            float4 bv = *(const float4*)&w[(size_t)(n0 + row) * CC + k0 + kv];
            split_tf32(bv.x, Bh[(kv + 0) * GP + row], Bl[(kv + 0) * GP + row]);
            split_tf32(bv.y, Bh[(kv + 1) * GP + row], Bl[(kv + 1) * GP + row]);
            split_tf32(bv.z, Bh[(kv + 2) * GP + row], Bl[(kv + 2) * GP + row]);
            split_tf32(bv.w, Bh[(kv + 3) * GP + row], Bl[(kv + 3) * GP + row]);
        }
        __syncthreads();
        GEMM_MAINLOOP(Ah, Al, Bh, Bl, acc, warp_m, warp_n, g, t)
        __syncthreads();
    }

#pragma unroll
    for (int mt = 0; mt < 4; ++mt) {
#pragma unroll
        for (int nt = 0; nt < 4; ++nt) {
#pragma unroll
            for (int r = 0; r < 4; ++r) {
                const int m  = m0 + warp_m * 64 + mt * 16 + g + ((r >= 2) ? 8 : 0);
                const int jg = n0 + warp_n * 32 + nt * 8 + 2 * t + (r & 1);
                out[(size_t)m * CC + jg] = acc[mt][nt][r] + bias[jg];
            }
        }
    }
}

// ---------------------------------------------------------------------------
extern "C" void kernel_launch(void* const* d_in, const int* in_sizes, int n_in,
                              void* d_out, int out_size)
{
    (void)in_sizes; (void)n_in; (void)out_size;
    const float* x      = (const float*)d_in[0];   // [2,2048,1024]
    const float* w_qkv  = (const float*)d_in[1];   // [3072,1024]
    const float* w_proj = (const float*)d_in[2];   // [1024,1024]
    const float* b_proj = (const float*)d_in[3];   // [1024]
    float* out = (float*)d_out;                    // [2,2048,1024]

    // QKV projection + scatter to [B,H,N,D] (3xTF32 mma)
    qkv_gemm_kernel<<<dim3(3 * CC / 128, BB * NN / 128), 256>>>(x, w_qkv);

    // Flash attention (tf32 mma), per (b,h), 128-row Q tiles
    cudaFuncSetAttribute(attn_mma_kernel,
                         cudaFuncAttributeMaxDynamicSharedMemorySize,
                         ATTN_SMEM_BYTES);
    attn_mma_kernel<<<dim3(NN / 128, BB * HH), 256, ATTN_SMEM_BYTES>>>();

    // Output projection + bias (3xTF32 mma)
    proj_gemm_kernel<<<dim3(CC / 128, BB * NN / 128), 256>>>(w_proj, b_proj, out);
}